// round 16
// baseline (speedup 1.0000x reference)
#include <cuda_runtime.h>
#include <cuda.h>
#include <cuda_bf16.h>
#include <cstdint>
#include <cstddef>

// ============================================================
// BiRealLinear: out[m,n] = scale[n] * sum_k sign(x[m,k])*sign(w[n,k])
// M=8192, N=4096, K=4096
// Signs as e4m3 (+1=0x38, -1=0xB8): exact fp8 products, exact fp32 accum.
// gemm_tc : PERSISTENT 2-CTA-cluster cg2 tcgen05 fp8 GEMM, TMA cg2
//           producers. Pair tile 256x512, BK=128, 4-stage ring, split
//           stage barriers (fullA = A+B0, fullB = B1).
//           KEY CHANGE: D0/D1 MMA dispatches are INTERLEAVED so
//           consecutive dispatches alternate accumulators — hides the
//           same-accumulator dependent-dispatch latency that was
//           leaving the tensor pipe ~50% idle.
// phase_shift_kernel : no-op to align ncu -s 5 onto gemm_tc.
// fb path : quant kernels + tiled FMA insurance (non-'a' pass only).
// ============================================================

#define M_DIM 8192
#define N_DIM 4096
#define K_DIM 4096

#if defined(__CUDA_ARCH_FEAT_SM103_ALL) || defined(__CUDA_ARCH_FEAT_SM100_ALL)
#define HAS_TCGEN05 1
#else
#define HAS_TCGEN05 0
#endif

// -------- scratch (device globals: no allocation allowed) --------
__device__ uint8_t g_xq[(size_t)M_DIM * K_DIM];   // 32 MB e4m3 signs
__device__ uint8_t g_wq[(size_t)N_DIM * K_DIM];   // 16 MB e4m3 signs
__device__ float   g_scale[N_DIM];

// ---------------- common helpers ----------------
__device__ __forceinline__ uint32_t smem_u32(const void* p) {
    uint32_t a;
    asm("{ .reg .u64 t; cvta.to.shared.u64 t, %1; cvt.u32.u64 %0, t; }"
        : "=r"(a) : "l"(p));
    return a;
}

// e4m3 sign byte: +1.0 -> 0x38, -1.0 -> 0xB8
__device__ __forceinline__ uint32_t sgn8(float v) { return (v > 0.f) ? 0x38u : 0xB8u; }
__device__ __forceinline__ uint32_t pack4(float4 v) {
    return sgn8(v.x) | (sgn8(v.y) << 8) | (sgn8(v.z) << 16) | (sgn8(v.w) << 24);
}

// ---------------- phase-shift no-op (ncu capture alignment) ----------------
__global__ void phase_shift_kernel() {}

// ---------------- quantize kernels ----------------
__global__ void quant_x_kernel(const float* __restrict__ x) {
    size_t gid = (size_t)blockIdx.x * blockDim.x + threadIdx.x;
    const float4* xp = (const float4*)x;
    float4 a = __ldcs(&xp[gid * 2]);
    float4 b = __ldcs(&xp[gid * 2 + 1]);
    ((uint2*)g_xq)[gid] = make_uint2(pack4(a), pack4(b));
}

__global__ void quant_w_fused_kernel(const float* __restrict__ w) {
    const int row = blockIdx.x;
    const float4* wr = (const float4*)(w + (size_t)row * K_DIM);
    uint32_t* outw = (uint32_t*)(g_wq + (size_t)row * K_DIM);
    float s = 0.f;
#pragma unroll
    for (int j = 0; j < 4; j++) {
        int i = threadIdx.x + j * 256;
        float4 v = __ldcs(&wr[i]);
        s += fabsf(v.x) + fabsf(v.y) + fabsf(v.z) + fabsf(v.w);
        outw[i] = pack4(v);
    }
#pragma unroll
    for (int o = 16; o; o >>= 1) s += __shfl_xor_sync(0xFFFFFFFFu, s, o);
    __shared__ float sh[8];
    if ((threadIdx.x & 31) == 0) sh[threadIdx.x >> 5] = s;
    __syncthreads();
    if (threadIdx.x == 0) {
        float t = 0.f;
#pragma unroll
        for (int j = 0; j < 8; j++) t += sh[j];
        g_scale[row] = t * (1.0f / (float)K_DIM);
    }
}

// ---------------- GEMM layout ----------------
#define PAIR_BM 256
#define PAIR_BN 512
#define BK 128
#define N_CHUNKS (K_DIM / BK)             // 32 per tile
#define NT_X (N_DIM / PAIR_BN)            // 8
#define NTILES (NT_X * (M_DIM / PAIR_BM)) // 256
#define TC_GRID 148
#define N_CLUSTERS (TC_GRID / 2)          // 74
#define A_TILE_BYTES (128 * 128)          // 16 KB
#define B_TILE_BYTES (256 * 128)          // 32 KB
#define STAGE_BYTES (A_TILE_BYTES + B_TILE_BYTES)  // 48 KB
#define N_STAGES 4
#define TX_A_PAIR 65536                   // A + B-half0, both CTAs (64 KB)
#define TX_B_PAIR 32768                   // B-half1, both CTAs (32 KB)
#define SM_TMEM     0
#define SM_FULLA    8                     // 4 mbars (leader): A + B0
#define SM_FULLB    40                    // 4 mbars (leader): B1
#define SM_DONE     72                    // 4 done mbars (cg2 commit multicast)
#define SM_DMMA     104                   // tile-MMAs-done
#define SM_EPI      112                   // epilogue-done (count 512, CTA0)
#define SM_TILES    2048
#define GEMM_SMEM_REQ (SM_TILES + N_STAGES * STAGE_BYTES)  // 198656 B
#define TC_THREADS 320
// idesc cg2: f32 accum (1<<4), e4m3 x e4m3 (0), N=256 -> 32<<17, M=256 -> 16<<24
#define GEMM_IDESC_CG2 0x10400010u

#if HAS_TCGEN05
// ---------------- tcgen05 / mbarrier / TMA helpers ----------------
__device__ __forceinline__ uint32_t elect_one() {
    uint32_t pred;
    asm volatile(
        "{\n\t.reg .pred p;\n\t"
        "elect.sync _|p, 0xFFFFFFFF;\n\t"
        "selp.b32 %0, 1, 0, p;\n\t}"
        : "=r"(pred));
    return pred;
}

__device__ __forceinline__ uint32_t cluster_rank() {
    uint32_t r;
    asm("mov.u32 %0, %%cluster_ctarank;" : "=r"(r));
    return r;
}

#define MBARRIER_INIT(addr, cnt) \
    asm volatile("mbarrier.init.shared.b64 [%0], %1;" :: "r"(addr), "r"(cnt) : "memory")

#define MBARRIER_EXPECT_TX(addr, bytes) \
    asm volatile("mbarrier.arrive.expect_tx.shared.b64 _, [%0], %1;" \
                 :: "r"((uint32_t)(addr)), "r"((uint32_t)(bytes)) : "memory")

#define MBARRIER_ARRIVE_CLUSTER(local_addr, rank) \
    asm volatile( \
        "{\n\t.reg .b32 remAddr;\n\t" \
        "mapa.shared::cluster.u32 remAddr, %0, %1;\n\t" \
        "mbarrier.arrive.shared::cluster.b64 _, [remAddr];\n\t}" \
        :: "r"((uint32_t)(local_addr)), "r"((uint32_t)(rank)) : "memory")

#define MBARRIER_WAIT_PARITY(mbar_addr, phase_parity) do {                         \
    uint32_t _mbar = (uint32_t)(mbar_addr);                                        \
    uint32_t _parity = (uint32_t)(phase_parity);                                   \
    uint32_t _done;                                                                \
    asm volatile(                                                                  \
        "{\n\t.reg .pred p;\n\t"                                                   \
        "mbarrier.try_wait.parity.acquire.cta.shared::cta.b64 p, [%1], %2;\n\t"    \
        "selp.b32 %0, 1, 0, p;\n\t}"                                               \
        : "=r"(_done) : "r"(_mbar), "r"(_parity) : "memory");                      \
    if (!_done) {                                                                  \
        asm volatile(                                                              \
            "{\n\t.reg .pred P1;\n\t"                                              \
            "WAIT_LOOP_%=:\n\t"                                                    \
            "mbarrier.try_wait.parity.acquire.cta.shared::cta.b64 P1, [%0], %1, 0x989680;\n\t" \
            "@P1 bra.uni WAIT_DONE_%=;\n\t"                                        \
            "bra.uni WAIT_LOOP_%=;\n\t"                                            \
            "WAIT_DONE_%=:\n\t}"                                                   \
            :: "r"(_mbar), "r"(_parity) : "memory");                               \
    }                                                                              \
} while (0)

// cta_group::2 TMA load: complete_tx targets the LEADER CTA's mbarrier
// (bit 24 cleared per Sm100MmaPeerBitMask). Both CTAs execute this.
#define TMA_LOAD_2D_CG2(smem_addr, map_ptr, cx, cy, mbar_local) \
    asm volatile( \
        "{\n\t.reg .b32 leaderBar;\n\t" \
        "and.b32 leaderBar, %4, 0xFEFFFFFF;\n\t" \
        "cp.async.bulk.tensor.2d.cta_group::2.shared::cluster.global.tile" \
        ".mbarrier::complete_tx::bytes [%0], [%1, {%2, %3}], [leaderBar];\n\t}" \
        :: "r"((uint32_t)(smem_addr)), "l"(map_ptr), \
           "r"((int32_t)(cx)), "r"((int32_t)(cy)), "r"((uint32_t)(mbar_local)) \
        : "memory")

#define CLUSTER_SYNC() do { \
    asm volatile("barrier.cluster.arrive.aligned;" ::: "memory"); \
    asm volatile("barrier.cluster.wait.aligned;" ::: "memory"); \
} while (0)

#define TCGEN05_ALLOC_CG2(smem_addr, nCols) \
    asm volatile("tcgen05.alloc.cta_group::2.sync.aligned.shared::cta.b32 [%0], %1;" \
                 :: "r"((uint32_t)(smem_addr)), "r"((uint32_t)(nCols)) : "memory")
#define TCGEN05_DEALLOC_CG2(tmem_addr, nCols) \
    asm volatile("tcgen05.dealloc.cta_group::2.sync.aligned.b32 %0, %1;" \
                 :: "r"(tmem_addr), "r"((uint32_t)(nCols)))
#define TCGEN05_RELINQUISH_CG2() \
    asm volatile("tcgen05.relinquish_alloc_permit.cta_group::2.sync.aligned;")
#define TCGEN05_COMMIT_MC_CG2(mbar_addr, mask) \
    asm volatile("tcgen05.commit.cta_group::2.mbarrier::arrive::one.shared::cluster.multicast::cluster.b64 [%0], %1;" \
                 :: "r"((uint32_t)(mbar_addr)), "h"((uint16_t)(mask)) : "memory")
#define TCGEN05_WAIT_LD() \
    asm volatile("tcgen05.wait::ld.sync.aligned;" ::: "memory")
#define TCGEN05_FENCE_BEFORE() \
    asm volatile("tcgen05.fence::before_thread_sync;" ::: "memory")
#define TCGEN05_FENCE_AFTER() \
    asm volatile("tcgen05.fence::after_thread_sync;" ::: "memory")

#define TCGEN05_LD_32X32B_X32(r, tmem_addr) \
    asm volatile( \
        "tcgen05.ld.sync.aligned.32x32b.x32.b32 " \
        "{%0, %1, %2, %3, %4, %5, %6, %7, " \
        " %8, %9, %10, %11, %12, %13, %14, %15, " \
        " %16, %17, %18, %19, %20, %21, %22, %23, " \
        " %24, %25, %26, %27, %28, %29, %30, %31}, [%32];" \
        : "=r"((r)[0]),  "=r"((r)[1]),  "=r"((r)[2]),  "=r"((r)[3]), \
          "=r"((r)[4]),  "=r"((r)[5]),  "=r"((r)[6]),  "=r"((r)[7]), \
          "=r"((r)[8]),  "=r"((r)[9]),  "=r"((r)[10]), "=r"((r)[11]), \
          "=r"((r)[12]), "=r"((r)[13]), "=r"((r)[14]), "=r"((r)[15]), \
          "=r"((r)[16]), "=r"((r)[17]), "=r"((r)[18]), "=r"((r)[19]), \
          "=r"((r)[20]), "=r"((r)[21]), "=r"((r)[22]), "=r"((r)[23]), \
          "=r"((r)[24]), "=r"((r)[25]), "=r"((r)[26]), "=r"((r)[27]), \
          "=r"((r)[28]), "=r"((r)[29]), "=r"((r)[30]), "=r"((r)[31]) \
        : "r"(tmem_addr))

static __device__ __forceinline__ uint64_t make_smem_desc(uint32_t addr) {
    const uint64_t base =
        (uint64_t(2) << 61) | (uint64_t(1) << 46) | (uint64_t(64) << 32) | (uint64_t(1) << 16);
    return base | ((uint64_t)(addr >> 4) & 0x3FFF);
}

__device__ __forceinline__ void mma_f8_ss_cg2(uint32_t d_tmem, uint64_t a_desc, uint64_t b_desc,
                                              uint32_t idesc, bool acc) {
    uint32_t en = acc ? 1u : 0u;
    asm volatile(
        "{\n\t.reg .pred p;\n\t"
        "setp.ne.u32 p, %5, 0;\n\t"
        "tcgen05.mma.cta_group::2.kind::f8f6f4 [%0], %1, %2, %3, "
        "{%4, %4, %4, %4, %4, %4, %4, %4}, p;\n\t}"
        :: "r"(d_tmem), "l"(a_desc), "l"(b_desc), "r"(idesc), "r"(0u), "r"(en)
        : "memory");
}
#endif  // HAS_TCGEN05

// ======================= gemm_tc: persistent cg2, interleaved MMA chains =======================
__global__ void __launch_bounds__(TC_THREADS)
gemm_tc(float* __restrict__ out,
        const __grid_constant__ CUtensorMap tma_a,
        const __grid_constant__ CUtensorMap tma_b) {
#if HAS_TCGEN05
    extern __shared__ char smem[];
    uint32_t smem_base = smem_u32(smem);
    const int tid = threadIdx.x;
    const int wid = tid >> 5;              // 0 MMA issuer (CTA0), 1 TMA producer, 2..9 epilogue
    const int lid = tid & 31;
    const uint32_t rank = cluster_rank();

    if (wid == 0) TCGEN05_ALLOC_CG2(smem_base + SM_TMEM, 512);
    if (tid == 0) {
#pragma unroll
        for (int i = 0; i < N_STAGES; i++) {
            MBARRIER_INIT(smem_base + SM_FULLA + i * 8, 1);
            MBARRIER_INIT(smem_base + SM_FULLB + i * 8, 1);
            MBARRIER_INIT(smem_base + SM_DONE + i * 8, 1);
        }
        MBARRIER_INIT(smem_base + SM_DMMA, 1);
        MBARRIER_INIT(smem_base + SM_EPI, 512);
    }
    __syncthreads();
    uint32_t tmem_base;
    asm volatile("ld.shared.b32 %0, [%1];" : "=r"(tmem_base) : "r"(smem_base + SM_TMEM));
    if (wid == 0) TCGEN05_RELINQUISH_CG2();
    CLUSTER_SYNC();                         // mbarriers visible cluster-wide

    const uint32_t tiles = smem_base + SM_TILES;
    const int pid = blockIdx.x >> 1;        // cluster id

    if (wid == 1) {
        // ================= TMA producer (both CTAs, elected lane) =================
        if (elect_one()) {
            int s = 0;
            int pd0 = 0, pd1 = 0, pd2 = 0, pd3 = 0;
            uint32_t gc = 0;
            for (int t = pid; t < NTILES; t += N_CLUSTERS) {
                const int n0 = (t & (NT_X - 1)) * PAIR_BN;
                const int m0 = (t >> 3) * PAIR_BM;
                const int ya  = m0 + (int)rank * 128;
                const int yb0 = n0 + (int)rank * 128;
                const int yb1 = n0 + 256 + (int)rank * 128;
                for (int c = 0; c < N_CHUNKS; c++) {
                    if (gc >= N_STAGES) {   // stage free when its MMAs are done
                        if (s == 0)      { MBARRIER_WAIT_PARITY(smem_base + SM_DONE + 0,  pd0); pd0 ^= 1; }
                        else if (s == 1) { MBARRIER_WAIT_PARITY(smem_base + SM_DONE + 8,  pd1); pd1 ^= 1; }
                        else if (s == 2) { MBARRIER_WAIT_PARITY(smem_base + SM_DONE + 16, pd2); pd2 ^= 1; }
                        else             { MBARRIER_WAIT_PARITY(smem_base + SM_DONE + 24, pd3); pd3 ^= 1; }
                    }
                    const uint32_t fullA = smem_base + SM_FULLA + s * 8;
                    const uint32_t fullB = smem_base + SM_FULLB + s * 8;
                    const uint32_t At = tiles + s * STAGE_BYTES;
                    const uint32_t Bt = At + A_TILE_BYTES;
                    const int kb = c * BK;
                    if (rank == 0) {
                        MBARRIER_EXPECT_TX(fullA, TX_A_PAIR);
                        MBARRIER_EXPECT_TX(fullB, TX_B_PAIR);
                    }
                    TMA_LOAD_2D_CG2(At,         &tma_a, kb, ya,  fullA);
                    TMA_LOAD_2D_CG2(Bt,         &tma_b, kb, yb0, fullA);
                    TMA_LOAD_2D_CG2(Bt + 16384, &tma_b, kb, yb1, fullB);
                    s = (s + 1) & 3;
                    gc++;
                }
            }
        }
    } else if (wid == 0 && rank == 0) {
        // ================= MMA issuer (CTA0 warp0, elected lane) =================
        if (elect_one()) {
            int s = 0;
            int pa0 = 0, pa1 = 0, pa2 = 0, pa3 = 0;   // fullA parities
            int pb0 = 0, pb1 = 0, pb2 = 0, pb3 = 0;   // fullB parities
            int ep_ph = 0;
            bool first_tile = true;
            for (int t = pid; t < NTILES; t += N_CLUSTERS) {
                if (!first_tile) {          // TMEM of previous tile must be read out
                    MBARRIER_WAIT_PARITY(smem_base + SM_EPI, ep_ph); ep_ph ^= 1;
                    TCGEN05_FENCE_AFTER();
                }
                first_tile = false;
                for (int c = 0; c < N_CHUNKS; c++) {
                    const uint32_t sb = tiles + s * STAGE_BYTES;
                    uint64_t ad  = make_smem_desc(sb);
                    uint64_t bd0 = make_smem_desc(sb + A_TILE_BYTES);
                    uint64_t bd1 = bd0 + 1024;        // +16 KB (N-half1)
                    const bool acc0 = (c > 0);
                    // wait A + B-half0; fire first D0 dispatch immediately
                    if (s == 0)      { MBARRIER_WAIT_PARITY(smem_base + SM_FULLA + 0,  pa0); pa0 ^= 1; }
                    else if (s == 1) { MBARRIER_WAIT_PARITY(smem_base + SM_FULLA + 8,  pa1); pa1 ^= 1; }
                    else if (s == 2) { MBARRIER_WAIT_PARITY(smem_base + SM_FULLA + 16, pa2); pa2 ^= 1; }
                    else             { MBARRIER_WAIT_PARITY(smem_base + SM_FULLA + 24, pa3); pa3 ^= 1; }
                    mma_f8_ss_cg2(tmem_base, ad, bd0, GEMM_IDESC_CG2, acc0);
                    // wait B-half1, then INTERLEAVE the two accumulator chains:
                    // D1ks0, D0ks1, D1ks1, D0ks2, D1ks2, D0ks3, D1ks3
                    if (s == 0)      { MBARRIER_WAIT_PARITY(smem_base + SM_FULLB + 0,  pb0); pb0 ^= 1; }
                    else if (s == 1) { MBARRIER_WAIT_PARITY(smem_base + SM_FULLB + 8,  pb1); pb1 ^= 1; }
                    else if (s == 2) { MBARRIER_WAIT_PARITY(smem_base + SM_FULLB + 16, pb2); pb2 ^= 1; }
                    else             { MBARRIER_WAIT_PARITY(smem_base + SM_FULLB + 24, pb3); pb3 ^= 1; }
                    mma_f8_ss_cg2(tmem_base + 256, ad, bd1, GEMM_IDESC_CG2, acc0);
#pragma unroll
                    for (int ks = 1; ks < 4; ks++) {
                        mma_f8_ss_cg2(tmem_base,       ad + ks * 2, bd0 + ks * 2,
                                      GEMM_IDESC_CG2, true);
                        mma_f8_ss_cg2(tmem_base + 256, ad + ks * 2, bd1 + ks * 2,
                                      GEMM_IDESC_CG2, true);
                    }
                    TCGEN05_COMMIT_MC_CG2(smem_base + SM_DONE + s * 8, 0x3);
                    s = (s + 1) & 3;
                }
                TCGEN05_COMMIT_MC_CG2(smem_base + SM_DMMA, 0x3);   // tile done (both CTAs)
            }
        }
    } else if (wid == 0) {
        // CTA1 warp0: idle in mainloop
    } else {
        // ================= epilogue warps (2..9, both CTAs) =================
        const int sub     = wid & 3;            // TMEM subpartition = wid % 4
        const int colhalf = (wid - 2) >> 2;     // 0: cols 0-255, 1: cols 256-511
        int dm_ph = 0;
        for (int t = pid; t < NTILES; t += N_CLUSTERS) {
            const int n0 = (t & (NT_X - 1)) * PAIR_BN;
            const int m0 = (t >> 3) * PAIR_BM;
            MBARRIER_WAIT_PARITY(smem_base + SM_DMMA, dm_ph); dm_ph ^= 1;
            TCGEN05_FENCE_AFTER();
            const int row = m0 + (int)rank * 128 + sub * 32 + lid;
            const uint32_t dbase = tmem_base + colhalf * 256;
            float* orow = out + (size_t)row * N_DIM + n0 + colhalf * 256;
            const float* scol = g_scale + n0 + colhalf * 256;
#pragma unroll
            for (int c0 = 0; c0 < 256; c0 += 64) {   // pipelined: 2 LDTMs per wait
                uint32_t dr0[32], dr1[32];
                TCGEN05_LD_32X32B_X32(dr0, dbase + c0);
                TCGEN05_LD_32X32B_X32(dr1, dbase + c0 + 32);
                TCGEN05_WAIT_LD();
#pragma unroll
                for (int j = 0; j < 32; j += 4) {
                    const float4 sv = *(const float4*)(scol + c0 + j);
                    float4 v;
                    v.x = __uint_as_float(dr0[j + 0]) * sv.x;
                    v.y = __uint_as_float(dr0[j + 1]) * sv.y;
                    v.z = __uint_as_float(dr0[j + 2]) * sv.z;
                    v.w = __uint_as_float(dr0[j + 3]) * sv.w;
                    __stcs((float4*)(orow + c0 + j), v);
                }
#pragma unroll
                for (int j = 0; j < 32; j += 4) {
                    const float4 sv = *(const float4*)(scol + c0 + 32 + j);
                    float4 v;
                    v.x = __uint_as_float(dr1[j + 0]) * sv.x;
                    v.y = __uint_as_float(dr1[j + 1]) * sv.y;
                    v.z = __uint_as_float(dr1[j + 2]) * sv.z;
                    v.w = __uint_as_float(dr1[j + 3]) * sv.w;
                    __stcs((float4*)(orow + c0 + 32 + j), v);
                }
            }
            TCGEN05_FENCE_BEFORE();
            MBARRIER_ARRIVE_CLUSTER(smem_base + SM_EPI, 0);   // -> CTA0 epi (count 512)
        }
    }

    __syncthreads();
    CLUSTER_SYNC();
    if (wid == 0) TCGEN05_DEALLOC_CG2(tmem_base, 512);
    CLUSTER_SYNC();
#else
    (void)out; (void)tma_a; (void)tma_b;   // stub in non-'a' pass
#endif
}

// ======================= gemm_fb: insurance path (slow, correct) =======================
__global__ void __launch_bounds__(256)
gemm_fb(float* __restrict__ out) {
#if !HAS_TCGEN05
    __shared__ uint8_t As[64][64];
    __shared__ uint8_t Bs[64][64];
    const int tid = threadIdx.x;
    const int tx = tid & 15, ty = tid >> 4;
    const int n0 = blockIdx.x * 64, m0 = blockIdx.y * 64;
    const int lrow = tid >> 2;
    const int lcol = (tid & 3) * 16;

    float acc[4][4];
#pragma unroll
    for (int i = 0; i < 4; i++)
#pragma unroll
        for (int j = 0; j < 4; j++) acc[i][j] = 0.f;

    for (int kb = 0; kb < K_DIM; kb += 64) {
        *(uint4*)&As[lrow][lcol] =
            *(const uint4*)(g_xq + (size_t)(m0 + lrow) * K_DIM + kb + lcol);
        *(uint4*)&Bs[lrow][lcol] =
            *(const uint4*)(g_wq + (size_t)(n0 + lrow) * K_DIM + kb + lcol);
        __syncthreads();
#pragma unroll 8
        for (int k = 0; k < 64; k++) {
            float a[4], b[4];
#pragma unroll
            for (int i = 0; i < 4; i++) a[i] = (As[ty * 4 + i][k] & 0x80) ? -1.f : 1.f;
#pragma unroll
            for (int j = 0; j < 4; j++) b[j] = (Bs[tx * 4 + j][k] & 0x80) ? -1.f : 1.f;
#pragma unroll
            for (int i = 0; i < 4; i++)
#pragma unroll
                for (int j = 0; j < 4; j++) acc[i][j] += a[i] * b[j];
        }
        __syncthreads();
    }
#pragma unroll
    for (int i = 0; i < 4; i++)
#pragma unroll
        for (int j = 0; j < 4; j++) {
            const int col = n0 + tx * 4 + j;
            out[(size_t)(m0 + ty * 4 + i) * N_DIM + col] = acc[i][j] * g_scale[col];
        }
#else
    (void)out;
#endif
}

// ---------------- launch ----------------
typedef CUresult (*encode_fn_t)(CUtensorMap*, CUtensorMapDataType, cuuint32_t, void*,
                                const cuuint64_t*, const cuuint64_t*, const cuuint32_t*,
                                const cuuint32_t*, CUtensorMapInterleave, CUtensorMapSwizzle,
                                CUtensorMapL2promotion, CUtensorMapFloatOOBfill);

extern "C" void kernel_launch(void* const* d_in, const int* in_sizes, int n_in,
                              void* d_out, int out_size) {
    (void)in_sizes; (void)n_in; (void)out_size;
    const float* x = (const float*)d_in[0];
    const float* w = (const float*)d_in[1];
    float* out = (float*)d_out;

    phase_shift_kernel<<<1, 32>>>();   // ncu capture alignment (no-op)

    quant_x_kernel<<<(int)((M_DIM * (size_t)K_DIM / 8) / 256), 256>>>(x);
    quant_w_fused_kernel<<<N_DIM, 256>>>(w);

    cudaFuncAttributes fa{};
    cudaFuncGetAttributes(&fa, gemm_tc);

    if (fa.numRegs > 24) {
        encode_fn_t enc = nullptr;
        cudaDriverEntryPointQueryResult qr;
        cudaGetDriverEntryPoint("cuTensorMapEncodeTiled", (void**)&enc,
                                cudaEnableDefault, &qr);
        void* xq_ptr = nullptr; void* wq_ptr = nullptr;
        cudaGetSymbolAddress(&xq_ptr, g_xq);
        cudaGetSymbolAddress(&wq_ptr, g_wq);

        CUtensorMap map_a{}, map_b{};
        {
            cuuint64_t dims[2]  = {(cuuint64_t)K_DIM, (cuuint64_t)M_DIM};
            cuuint64_t strides[1] = {(cuuint64_t)K_DIM};
            cuuint32_t box[2]   = {128, 128};
            cuuint32_t elem[2]  = {1, 1};
            enc(&map_a, CU_TENSOR_MAP_DATA_TYPE_UINT8, 2, xq_ptr,
                dims, strides, box, elem,
                CU_TENSOR_MAP_INTERLEAVE_NONE, CU_TENSOR_MAP_SWIZZLE_128B,
                CU_TENSOR_MAP_L2_PROMOTION_L2_128B, CU_TENSOR_MAP_FLOAT_OOB_FILL_NONE);
        }
        {
            cuuint64_t dims[2]  = {(cuuint64_t)K_DIM, (cuuint64_t)N_DIM};
            cuuint64_t strides[1] = {(cuuint64_t)K_DIM};
            cuuint32_t box[2]   = {128, 128};
            cuuint32_t elem[2]  = {1, 1};
            enc(&map_b, CU_TENSOR_MAP_DATA_TYPE_UINT8, 2, wq_ptr,
                dims, strides, box, elem,
                CU_TENSOR_MAP_INTERLEAVE_NONE, CU_TENSOR_MAP_SWIZZLE_128B,
                CU_TENSOR_MAP_L2_PROMOTION_L2_128B, CU_TENSOR_MAP_FLOAT_OOB_FILL_NONE);
        }

        cudaFuncSetAttribute(gemm_tc, cudaFuncAttributeMaxDynamicSharedMemorySize,
                             GEMM_SMEM_REQ);
        cudaLaunchConfig_t cfg = {};
        cfg.gridDim = dim3(TC_GRID, 1, 1);
        cfg.blockDim = dim3(TC_THREADS, 1, 1);
        cfg.dynamicSmemBytes = GEMM_SMEM_REQ;
        cfg.stream = 0;
        cudaLaunchAttribute attrs[1];
        attrs[0].id = cudaLaunchAttributeClusterDimension;
        attrs[0].val.clusterDim.x = 2;
        attrs[0].val.clusterDim.y = 1;
        attrs[0].val.clusterDim.z = 1;
        cfg.attrs = attrs;
        cfg.numAttrs = 1;
        cudaLaunchKernelEx(&cfg, gemm_tc, out, map_a, map_b);
    } else {
        dim3 grid_fb(N_DIM / 64, M_DIM / 64);
        gemm_fb<<<grid_fb, 256>>>(out);
    }
}

// round 17
// speedup vs baseline: 1.0174x; 1.0174x over previous
#include <cuda_runtime.h>
#include <cuda.h>
#include <cuda_bf16.h>
#include <cstdint>
#include <cstddef>

// ============================================================
// BiRealLinear: out[m,n] = scale[n] * sum_k sign(x[m,k])*sign(w[n,k])
// M=8192, N=4096, K=4096
// Signs as e4m3 (+1=0x38, -1=0xB8): exact fp8 products, exact fp32 accum.
// gemm_tc : PERSISTENT 2-CTA-cluster cg2 tcgen05 fp8 GEMM, TMA cg2
//           producers. Pair tile 256x512, BK=64, EIGHT 24KB stages
//           (same 192KB smem as 4x48KB) — doubles the latency-amortizing
//           runway of the commit->done->TMA->full pipeline cycle.
//           SW64 swizzle (64B rows): TMA SWIZZLE_64B + desc layout 4.
// phase_shift_kernel : no-op to align ncu -s 5 onto gemm_tc.
// fb path : quant kernels + tiled FMA insurance (non-'a' pass only).
// ============================================================

#define M_DIM 8192
#define N_DIM 4096
#define K_DIM 4096

#if defined(__CUDA_ARCH_FEAT_SM103_ALL) || defined(__CUDA_ARCH_FEAT_SM100_ALL)
#define HAS_TCGEN05 1
#else
#define HAS_TCGEN05 0
#endif

// -------- scratch (device globals: no allocation allowed) --------
__device__ uint8_t g_xq[(size_t)M_DIM * K_DIM];   // 32 MB e4m3 signs
__device__ uint8_t g_wq[(size_t)N_DIM * K_DIM];   // 16 MB e4m3 signs
__device__ float   g_scale[N_DIM];

// ---------------- common helpers ----------------
__device__ __forceinline__ uint32_t smem_u32(const void* p) {
    uint32_t a;
    asm("{ .reg .u64 t; cvta.to.shared.u64 t, %1; cvt.u32.u64 %0, t; }"
        : "=r"(a) : "l"(p));
    return a;
}

// e4m3 sign byte: +1.0 -> 0x38, -1.0 -> 0xB8
__device__ __forceinline__ uint32_t sgn8(float v) { return (v > 0.f) ? 0x38u : 0xB8u; }
__device__ __forceinline__ uint32_t pack4(float4 v) {
    return sgn8(v.x) | (sgn8(v.y) << 8) | (sgn8(v.z) << 16) | (sgn8(v.w) << 24);
}

// ---------------- phase-shift no-op (ncu capture alignment) ----------------
__global__ void phase_shift_kernel() {}

// ---------------- quantize kernels ----------------
__global__ void quant_x_kernel(const float* __restrict__ x) {
    size_t gid = (size_t)blockIdx.x * blockDim.x + threadIdx.x;
    const float4* xp = (const float4*)x;
    float4 a = __ldcs(&xp[gid * 2]);
    float4 b = __ldcs(&xp[gid * 2 + 1]);
    ((uint2*)g_xq)[gid] = make_uint2(pack4(a), pack4(b));
}

__global__ void quant_w_fused_kernel(const float* __restrict__ w) {
    const int row = blockIdx.x;
    const float4* wr = (const float4*)(w + (size_t)row * K_DIM);
    uint32_t* outw = (uint32_t*)(g_wq + (size_t)row * K_DIM);
    float s = 0.f;
#pragma unroll
    for (int j = 0; j < 4; j++) {
        int i = threadIdx.x + j * 256;
        float4 v = __ldcs(&wr[i]);
        s += fabsf(v.x) + fabsf(v.y) + fabsf(v.z) + fabsf(v.w);
        outw[i] = pack4(v);
    }
#pragma unroll
    for (int o = 16; o; o >>= 1) s += __shfl_xor_sync(0xFFFFFFFFu, s, o);
    __shared__ float sh[8];
    if ((threadIdx.x & 31) == 0) sh[threadIdx.x >> 5] = s;
    __syncthreads();
    if (threadIdx.x == 0) {
        float t = 0.f;
#pragma unroll
        for (int j = 0; j < 8; j++) t += sh[j];
        g_scale[row] = t * (1.0f / (float)K_DIM);
    }
}

// ---------------- GEMM layout ----------------
#define PAIR_BM 256
#define PAIR_BN 512
#define BK 64
#define N_CHUNKS (K_DIM / BK)             // 64 per tile
#define NT_X (N_DIM / PAIR_BN)            // 8
#define NTILES (NT_X * (M_DIM / PAIR_BM)) // 256
#define TC_GRID 148
#define N_CLUSTERS (TC_GRID / 2)          // 74
#define A_TILE_BYTES (128 * 64)           // 8 KB (this CTA's M-half, 64B rows)
#define B_HALF_BYTES (128 * 64)           // 8 KB per B half per CTA
#define STAGE_BYTES (A_TILE_BYTES + 2 * B_HALF_BYTES)  // 24 KB
#define N_STAGES 8
#define TX_A_PAIR 32768                   // A + B-half0, both CTAs (32 KB)
#define TX_B_PAIR 16384                   // B-half1, both CTAs (16 KB)
#define SM_TMEM     0
#define SM_FULLA    8                     // 8 mbars (leader): A + B0
#define SM_FULLB    72                    // 8 mbars (leader): B1
#define SM_DONE     136                   // 8 done mbars (cg2 commit multicast)
#define SM_DMMA     200                   // tile-MMAs-done
#define SM_EPI      208                   // epilogue-done (count 512, CTA0)
#define SM_TILES    2048
#define GEMM_SMEM_REQ (SM_TILES + N_STAGES * STAGE_BYTES)  // 198656 B (same as before)
#define TC_THREADS 320
// idesc cg2: f32 accum (1<<4), e4m3 x e4m3 (0), N=256 -> 32<<17, M=256 -> 16<<24
#define GEMM_IDESC_CG2 0x10400010u

#if HAS_TCGEN05
// ---------------- tcgen05 / mbarrier / TMA helpers ----------------
__device__ __forceinline__ uint32_t elect_one() {
    uint32_t pred;
    asm volatile(
        "{\n\t.reg .pred p;\n\t"
        "elect.sync _|p, 0xFFFFFFFF;\n\t"
        "selp.b32 %0, 1, 0, p;\n\t}"
        : "=r"(pred));
    return pred;
}

__device__ __forceinline__ uint32_t cluster_rank() {
    uint32_t r;
    asm("mov.u32 %0, %%cluster_ctarank;" : "=r"(r));
    return r;
}

#define MBARRIER_INIT(addr, cnt) \
    asm volatile("mbarrier.init.shared.b64 [%0], %1;" :: "r"(addr), "r"(cnt) : "memory")

#define MBARRIER_EXPECT_TX(addr, bytes) \
    asm volatile("mbarrier.arrive.expect_tx.shared.b64 _, [%0], %1;" \
                 :: "r"((uint32_t)(addr)), "r"((uint32_t)(bytes)) : "memory")

#define MBARRIER_ARRIVE_CLUSTER(local_addr, rank) \
    asm volatile( \
        "{\n\t.reg .b32 remAddr;\n\t" \
        "mapa.shared::cluster.u32 remAddr, %0, %1;\n\t" \
        "mbarrier.arrive.shared::cluster.b64 _, [remAddr];\n\t}" \
        :: "r"((uint32_t)(local_addr)), "r"((uint32_t)(rank)) : "memory")

#define MBARRIER_WAIT_PARITY(mbar_addr, phase_parity) do {                         \
    uint32_t _mbar = (uint32_t)(mbar_addr);                                        \
    uint32_t _parity = (uint32_t)(phase_parity);                                   \
    uint32_t _done;                                                                \
    asm volatile(                                                                  \
        "{\n\t.reg .pred p;\n\t"                                                   \
        "mbarrier.try_wait.parity.acquire.cta.shared::cta.b64 p, [%1], %2;\n\t"    \
        "selp.b32 %0, 1, 0, p;\n\t}"                                               \
        : "=r"(_done) : "r"(_mbar), "r"(_parity) : "memory");                      \
    if (!_done) {                                                                  \
        asm volatile(                                                              \
            "{\n\t.reg .pred P1;\n\t"                                              \
            "WAIT_LOOP_%=:\n\t"                                                    \
            "mbarrier.try_wait.parity.acquire.cta.shared::cta.b64 P1, [%0], %1, 0x989680;\n\t" \
            "@P1 bra.uni WAIT_DONE_%=;\n\t"                                        \
            "bra.uni WAIT_LOOP_%=;\n\t"                                            \
            "WAIT_DONE_%=:\n\t}"                                                   \
            :: "r"(_mbar), "r"(_parity) : "memory");                               \
    }                                                                              \
} while (0)

// cta_group::2 TMA load: complete_tx targets the LEADER CTA's mbarrier
// (bit 24 cleared per Sm100MmaPeerBitMask). Both CTAs execute this.
#define TMA_LOAD_2D_CG2(smem_addr, map_ptr, cx, cy, mbar_local) \
    asm volatile( \
        "{\n\t.reg .b32 leaderBar;\n\t" \
        "and.b32 leaderBar, %4, 0xFEFFFFFF;\n\t" \
        "cp.async.bulk.tensor.2d.cta_group::2.shared::cluster.global.tile" \
        ".mbarrier::complete_tx::bytes [%0], [%1, {%2, %3}], [leaderBar];\n\t}" \
        :: "r"((uint32_t)(smem_addr)), "l"(map_ptr), \
           "r"((int32_t)(cx)), "r"((int32_t)(cy)), "r"((uint32_t)(mbar_local)) \
        : "memory")

#define CLUSTER_SYNC() do { \
    asm volatile("barrier.cluster.arrive.aligned;" ::: "memory"); \
    asm volatile("barrier.cluster.wait.aligned;" ::: "memory"); \
} while (0)

#define TCGEN05_ALLOC_CG2(smem_addr, nCols) \
    asm volatile("tcgen05.alloc.cta_group::2.sync.aligned.shared::cta.b32 [%0], %1;" \
                 :: "r"((uint32_t)(smem_addr)), "r"((uint32_t)(nCols)) : "memory")
#define TCGEN05_DEALLOC_CG2(tmem_addr, nCols) \
    asm volatile("tcgen05.dealloc.cta_group::2.sync.aligned.b32 %0, %1;" \
                 :: "r"(tmem_addr), "r"((uint32_t)(nCols)))
#define TCGEN05_RELINQUISH_CG2() \
    asm volatile("tcgen05.relinquish_alloc_permit.cta_group::2.sync.aligned;")
#define TCGEN05_COMMIT_MC_CG2(mbar_addr, mask) \
    asm volatile("tcgen05.commit.cta_group::2.mbarrier::arrive::one.shared::cluster.multicast::cluster.b64 [%0], %1;" \
                 :: "r"((uint32_t)(mbar_addr)), "h"((uint16_t)(mask)) : "memory")
#define TCGEN05_WAIT_LD() \
    asm volatile("tcgen05.wait::ld.sync.aligned;" ::: "memory")
#define TCGEN05_FENCE_BEFORE() \
    asm volatile("tcgen05.fence::before_thread_sync;" ::: "memory")
#define TCGEN05_FENCE_AFTER() \
    asm volatile("tcgen05.fence::after_thread_sync;" ::: "memory")

#define TCGEN05_LD_32X32B_X32(r, tmem_addr) \
    asm volatile( \
        "tcgen05.ld.sync.aligned.32x32b.x32.b32 " \
        "{%0, %1, %2, %3, %4, %5, %6, %7, " \
        " %8, %9, %10, %11, %12, %13, %14, %15, " \
        " %16, %17, %18, %19, %20, %21, %22, %23, " \
        " %24, %25, %26, %27, %28, %29, %30, %31}, [%32];" \
        : "=r"((r)[0]),  "=r"((r)[1]),  "=r"((r)[2]),  "=r"((r)[3]), \
          "=r"((r)[4]),  "=r"((r)[5]),  "=r"((r)[6]),  "=r"((r)[7]), \
          "=r"((r)[8]),  "=r"((r)[9]),  "=r"((r)[10]), "=r"((r)[11]), \
          "=r"((r)[12]), "=r"((r)[13]), "=r"((r)[14]), "=r"((r)[15]), \
          "=r"((r)[16]), "=r"((r)[17]), "=r"((r)[18]), "=r"((r)[19]), \
          "=r"((r)[20]), "=r"((r)[21]), "=r"((r)[22]), "=r"((r)[23]), \
          "=r"((r)[24]), "=r"((r)[25]), "=r"((r)[26]), "=r"((r)[27]), \
          "=r"((r)[28]), "=r"((r)[29]), "=r"((r)[30]), "=r"((r)[31]) \
        : "r"(tmem_addr))

// SW64 K-major SMEM descriptor: layout=4 (SW64), version=1, SBO=32, LBO=1
// (SW64 atom = 8 rows x 64B = 512B; SBO 32*16=512B, LBO 1*16=16B)
static __device__ __forceinline__ uint64_t make_smem_desc_sw64(uint32_t addr) {
    const uint64_t base =
        (uint64_t(4) << 61) | (uint64_t(1) << 46) | (uint64_t(32) << 32) | (uint64_t(1) << 16);
    return base | ((uint64_t)(addr >> 4) & 0x3FFF);
}

__device__ __forceinline__ void mma_f8_ss_cg2(uint32_t d_tmem, uint64_t a_desc, uint64_t b_desc,
                                              uint32_t idesc, bool acc) {
    uint32_t en = acc ? 1u : 0u;
    asm volatile(
        "{\n\t.reg .pred p;\n\t"
        "setp.ne.u32 p, %5, 0;\n\t"
        "tcgen05.mma.cta_group::2.kind::f8f6f4 [%0], %1, %2, %3, "
        "{%4, %4, %4, %4, %4, %4, %4, %4}, p;\n\t}"
        :: "r"(d_tmem), "l"(a_desc), "l"(b_desc), "r"(idesc), "r"(0u), "r"(en)
        : "memory");
}
#endif  // HAS_TCGEN05

// ======================= gemm_tc: persistent cg2, 8-stage BK=64 ring =======================
__global__ void __launch_bounds__(TC_THREADS)
gemm_tc(float* __restrict__ out,
        const __grid_constant__ CUtensorMap tma_a,
        const __grid_constant__ CUtensorMap tma_b) {
#if HAS_TCGEN05
    extern __shared__ char smem[];
    uint32_t smem_base = smem_u32(smem);
    const int tid = threadIdx.x;
    const int wid = tid >> 5;              // 0 MMA issuer (CTA0), 1 TMA producer, 2..9 epilogue
    const int lid = tid & 31;
    const uint32_t rank = cluster_rank();

    if (wid == 0) TCGEN05_ALLOC_CG2(smem_base + SM_TMEM, 512);
    if (tid == 0) {
#pragma unroll
        for (int i = 0; i < N_STAGES; i++) {
            MBARRIER_INIT(smem_base + SM_FULLA + i * 8, 1);
            MBARRIER_INIT(smem_base + SM_FULLB + i * 8, 1);
            MBARRIER_INIT(smem_base + SM_DONE + i * 8, 1);
        }
        MBARRIER_INIT(smem_base + SM_DMMA, 1);
        MBARRIER_INIT(smem_base + SM_EPI, 512);
    }
    __syncthreads();
    uint32_t tmem_base;
    asm volatile("ld.shared.b32 %0, [%1];" : "=r"(tmem_base) : "r"(smem_base + SM_TMEM));
    if (wid == 0) TCGEN05_RELINQUISH_CG2();
    CLUSTER_SYNC();                         // mbarriers visible cluster-wide

    const uint32_t tiles = smem_base + SM_TILES;
    const int pid = blockIdx.x >> 1;        // cluster id

    if (wid == 1) {
        // ================= TMA producer (both CTAs, elected lane) =================
        if (elect_one()) {
            int s = 0;
            uint32_t pd = 0;                // done parity bitmask
            uint32_t gc = 0;
            for (int t = pid; t < NTILES; t += N_CLUSTERS) {
                const int n0 = (t & (NT_X - 1)) * PAIR_BN;
                const int m0 = (t >> 3) * PAIR_BM;
                const int ya  = m0 + (int)rank * 128;
                const int yb0 = n0 + (int)rank * 128;
                const int yb1 = n0 + 256 + (int)rank * 128;
                for (int c = 0; c < N_CHUNKS; c++) {
                    if (gc >= N_STAGES) {   // stage free when its MMAs are done
                        MBARRIER_WAIT_PARITY(smem_base + SM_DONE + s * 8, (pd >> s) & 1u);
                        pd ^= (1u << s);
                    }
                    const uint32_t fullA = smem_base + SM_FULLA + s * 8;
                    const uint32_t fullB = smem_base + SM_FULLB + s * 8;
                    const uint32_t At = tiles + s * STAGE_BYTES;
                    const uint32_t Bt = At + A_TILE_BYTES;
                    const int kb = c * BK;
                    if (rank == 0) {
                        MBARRIER_EXPECT_TX(fullA, TX_A_PAIR);
                        MBARRIER_EXPECT_TX(fullB, TX_B_PAIR);
                    }
                    TMA_LOAD_2D_CG2(At,        &tma_a, kb, ya,  fullA);
                    TMA_LOAD_2D_CG2(Bt,        &tma_b, kb, yb0, fullA);
                    TMA_LOAD_2D_CG2(Bt + 8192, &tma_b, kb, yb1, fullB);
                    s = (s + 1) & (N_STAGES - 1);
                    gc++;
                }
            }
        }
    } else if (wid == 0 && rank == 0) {
        // ================= MMA issuer (CTA0 warp0, elected lane) =================
        if (elect_one()) {
            int s = 0;
            uint32_t pa = 0, pb = 0;        // fullA / fullB parity bitmasks
            int ep_ph = 0;
            bool first_tile = true;
            for (int t = pid; t < NTILES; t += N_CLUSTERS) {
                if (!first_tile) {          // TMEM of previous tile must be read out
                    MBARRIER_WAIT_PARITY(smem_base + SM_EPI, ep_ph); ep_ph ^= 1;
                    TCGEN05_FENCE_AFTER();
                }
                first_tile = false;
                for (int c = 0; c < N_CHUNKS; c++) {
                    const uint32_t sb = tiles + s * STAGE_BYTES;
                    uint64_t ad  = make_smem_desc_sw64(sb);
                    uint64_t bd0 = make_smem_desc_sw64(sb + A_TILE_BYTES);
                    uint64_t bd1 = make_smem_desc_sw64(sb + A_TILE_BYTES + B_HALF_BYTES);
                    const bool acc0 = (c > 0);
                    MBARRIER_WAIT_PARITY(smem_base + SM_FULLA + s * 8, (pa >> s) & 1u);
                    pa ^= (1u << s);
                    mma_f8_ss_cg2(tmem_base, ad, bd0, GEMM_IDESC_CG2, acc0);
                    MBARRIER_WAIT_PARITY(smem_base + SM_FULLB + s * 8, (pb >> s) & 1u);
                    pb ^= (1u << s);
                    mma_f8_ss_cg2(tmem_base + 256, ad, bd1, GEMM_IDESC_CG2, acc0);
                    // ks=1 (desc +2 = +32B within 64B SW64 rows)
                    mma_f8_ss_cg2(tmem_base,       ad + 2, bd0 + 2, GEMM_IDESC_CG2, true);
                    mma_f8_ss_cg2(tmem_base + 256, ad + 2, bd1 + 2, GEMM_IDESC_CG2, true);
                    TCGEN05_COMMIT_MC_CG2(smem_base + SM_DONE + s * 8, 0x3);
                    s = (s + 1) & (N_STAGES - 1);
                }
                TCGEN05_COMMIT_MC_CG2(smem_base + SM_DMMA, 0x3);   // tile done (both CTAs)
            }
        }
    } else if (wid == 0) {
        // CTA1 warp0: idle in mainloop
    } else {
        // ================= epilogue warps (2..9, both CTAs) =================
        const int sub     = wid & 3;            // TMEM subpartition = wid % 4
        const int colhalf = (wid - 2) >> 2;     // 0: cols 0-255, 1: cols 256-511
        int dm_ph = 0;
        for (int t = pid; t < NTILES; t += N_CLUSTERS) {
            const int n0 = (t & (NT_X - 1)) * PAIR_BN;
            const int m0 = (t >> 3) * PAIR_BM;
            MBARRIER_WAIT_PARITY(smem_base + SM_DMMA, dm_ph); dm_ph ^= 1;
            TCGEN05_FENCE_AFTER();
            const int row = m0 + (int)rank * 128 + sub * 32 + lid;
            const uint32_t dbase = tmem_base + colhalf * 256;
            float* orow = out + (size_t)row * N_DIM + n0 + colhalf * 256;
            const float* scol = g_scale + n0 + colhalf * 256;
#pragma unroll
            for (int c0 = 0; c0 < 256; c0 += 64) {   // pipelined: 2 LDTMs per wait
                uint32_t dr0[32], dr1[32];
                TCGEN05_LD_32X32B_X32(dr0, dbase + c0);
                TCGEN05_LD_32X32B_X32(dr1, dbase + c0 + 32);
                TCGEN05_WAIT_LD();
#pragma unroll
                for (int j = 0; j < 32; j += 4) {
                    const float4 sv = *(const float4*)(scol + c0 + j);
                    float4 v;
                    v.x = __uint_as_float(dr0[j + 0]) * sv.x;
                    v.y = __uint_as_float(dr0[j + 1]) * sv.y;
                    v.z = __uint_as_float(dr0[j + 2]) * sv.z;
                    v.w = __uint_as_float(dr0[j + 3]) * sv.w;
                    __stcs((float4*)(orow + c0 + j), v);
                }
#pragma unroll
                for (int j = 0; j < 32; j += 4) {
                    const float4 sv = *(const float4*)(scol + c0 + 32 + j);
                    float4 v;
                    v.x = __uint_as_float(dr1[j + 0]) * sv.x;
                    v.y = __uint_as_float(dr1[j + 1]) * sv.y;
                    v.z = __uint_as_float(dr1[j + 2]) * sv.z;
                    v.w = __uint_as_float(dr1[j + 3]) * sv.w;
                    __stcs((float4*)(orow + c0 + 32 + j), v);
                }
            }
            TCGEN05_FENCE_BEFORE();
            MBARRIER_ARRIVE_CLUSTER(smem_base + SM_EPI, 0);   // -> CTA0 epi (count 512)
        }
    }

    __syncthreads();
    CLUSTER_SYNC();
    if (wid == 0) TCGEN05_DEALLOC_CG2(tmem_base, 512);
    CLUSTER_SYNC();
#else
    (void)out; (void)tma_a; (void)tma_b;   // stub in non-'a' pass
#endif
}

// ======================= gemm_fb: insurance path (slow, correct) =======================
__global__ void __launch_bounds__(256)
gemm_fb(float* __restrict__ out) {
#if !HAS_TCGEN05
    __shared__ uint8_t As[64][64];
    __shared__ uint8_t Bs[64][64];
    const int tid = threadIdx.x;
    const int tx = tid & 15, ty = tid >> 4;
    const int n0 = blockIdx.x * 64, m0 = blockIdx.y * 64;
    const int lrow = tid >> 2;
    const int lcol = (tid & 3) * 16;

    float acc[4][4];
#pragma unroll
    for (int i = 0; i < 4; i++)
#pragma unroll
        for (int j = 0; j < 4; j++) acc[i][j] = 0.f;

    for (int kb = 0; kb < K_DIM; kb += 64) {
        *(uint4*)&As[lrow][lcol] =
            *(const uint4*)(g_xq + (size_t)(m0 + lrow) * K_DIM + kb + lcol);
        *(uint4*)&Bs[lrow][lcol] =
            *(const uint4*)(g_wq + (size_t)(n0 + lrow) * K_DIM + kb + lcol);
        __syncthreads();
#pragma unroll 8
        for (int k = 0; k < 64; k++) {
            float a[4], b[4];
#pragma unroll
            for (int i = 0; i < 4; i++) a[i] = (As[ty * 4 + i][k] & 0x80) ? -1.f : 1.f;
#pragma unroll
            for (int j = 0; j < 4; j++) b[j] = (Bs[tx * 4 + j][k] & 0x80) ? -1.f : 1.f;
#pragma unroll
            for (int i = 0; i < 4; i++)
#pragma unroll
                for (int j = 0; j < 4; j++) acc[i][j] += a[i] * b[j];
        }
        __syncthreads();
    }
#pragma unroll
    for (int i = 0; i < 4; i++)
#pragma unroll
        for (int j = 0; j < 4; j++) {
            const int col = n0 + tx * 4 + j;
            out[(size_t)(m0 + ty * 4 + i) * N_DIM + col] = acc[i][j] * g_scale[col];
        }
#else
    (void)out;
#endif
}

// ---------------- launch ----------------
typedef CUresult (*encode_fn_t)(CUtensorMap*, CUtensorMapDataType, cuuint32_t, void*,
                                const cuuint64_t*, const cuuint64_t*, const cuuint32_t*,
                                const cuuint32_t*, CUtensorMapInterleave, CUtensorMapSwizzle,
                                CUtensorMapL2promotion, CUtensorMapFloatOOBfill);

extern "C" void kernel_launch(void* const* d_in, const int* in_sizes, int n_in,
                              void* d_out, int out_size) {
    (void)in_sizes; (void)n_in; (void)out_size;
    const float* x = (const float*)d_in[0];
    const float* w = (const float*)d_in[1];
    float* out = (float*)d_out;

    phase_shift_kernel<<<1, 32>>>();   // ncu capture alignment (no-op)

    quant_x_kernel<<<(int)((M_DIM * (size_t)K_DIM / 8) / 256), 256>>>(x);
    quant_w_fused_kernel<<<N_DIM, 256>>>(w);

    cudaFuncAttributes fa{};
    cudaFuncGetAttributes(&fa, gemm_tc);

    if (fa.numRegs > 24) {
        encode_fn_t enc = nullptr;
        cudaDriverEntryPointQueryResult qr;
        cudaGetDriverEntryPoint("cuTensorMapEncodeTiled", (void**)&enc,
                                cudaEnableDefault, &qr);
        void* xq_ptr = nullptr; void* wq_ptr = nullptr;
        cudaGetSymbolAddress(&xq_ptr, g_xq);
        cudaGetSymbolAddress(&wq_ptr, g_wq);

        CUtensorMap map_a{}, map_b{};
        {
            cuuint64_t dims[2]  = {(cuuint64_t)K_DIM, (cuuint64_t)M_DIM};
            cuuint64_t strides[1] = {(cuuint64_t)K_DIM};
            cuuint32_t box[2]   = {64, 128};        // 64B rows -> SW64
            cuuint32_t elem[2]  = {1, 1};
            enc(&map_a, CU_TENSOR_MAP_DATA_TYPE_UINT8, 2, xq_ptr,
                dims, strides, box, elem,
                CU_TENSOR_MAP_INTERLEAVE_NONE, CU_TENSOR_MAP_SWIZZLE_64B,
                CU_TENSOR_MAP_L2_PROMOTION_L2_128B, CU_TENSOR_MAP_FLOAT_OOB_FILL_NONE);
        }
        {
            cuuint64_t dims[2]  = {(cuuint64_t)K_DIM, (cuuint64_t)N_DIM};
            cuuint64_t strides[1] = {(cuuint64_t)K_DIM};
            cuuint32_t box[2]   = {64, 128};
            cuuint32_t elem[2]  = {1, 1};
            enc(&map_b, CU_TENSOR_MAP_DATA_TYPE_UINT8, 2, wq_ptr,
                dims, strides, box, elem,
                CU_TENSOR_MAP_INTERLEAVE_NONE, CU_TENSOR_MAP_SWIZZLE_64B,
                CU_TENSOR_MAP_L2_PROMOTION_L2_128B, CU_TENSOR_MAP_FLOAT_OOB_FILL_NONE);
        }

        cudaFuncSetAttribute(gemm_tc, cudaFuncAttributeMaxDynamicSharedMemorySize,
                             GEMM_SMEM_REQ);
        cudaLaunchConfig_t cfg = {};
        cfg.gridDim = dim3(TC_GRID, 1, 1);
        cfg.blockDim = dim3(TC_THREADS, 1, 1);
        cfg.dynamicSmemBytes = GEMM_SMEM_REQ;
        cfg.stream = 0;
        cudaLaunchAttribute attrs[1];
        attrs[0].id = cudaLaunchAttributeClusterDimension;
        attrs[0].val.clusterDim.x = 2;
        attrs[0].val.clusterDim.y = 1;
        attrs[0].val.clusterDim.z = 1;
        cfg.attrs = attrs;
        cfg.numAttrs = 1;
        cudaLaunchKernelEx(&cfg, gemm_tc, out, map_a, map_b);
    } else {
        dim3 grid_fb(N_DIM / 64, M_DIM / 64);
        gemm_fb<<<grid_fb, 256>>>(out);
    }
}